// round 2
// baseline (speedup 1.0000x reference)
#include <cuda_runtime.h>
#include <cuda_bf16.h>
#include <cstdint>

// ---------------- problem constants ----------------
static constexpr int B_ROWS = 65536;
static constexpr int D_DIM  = 512;   // K per pass
static constexpr int O_DIM  = 512;   // N
static constexpr int GRID_G = 16;

// ---------------- scratch (no allocs allowed) ----------------
__device__ __nv_bfloat16 g_A_hi[(size_t)B_ROWS * D_DIM];
__device__ __nv_bfloat16 g_A_lo[(size_t)B_ROWS * D_DIM];
__device__ __nv_bfloat16 g_M_hi[(size_t)O_DIM * D_DIM];
__device__ __nv_bfloat16 g_M_lo[(size_t)O_DIM * D_DIM];

// ---------------- kernel 1: spline + bf16 hi/lo split --------------------
__global__ void __launch_bounds__(256) spline_split_kernel(
    const float* __restrict__ x,
    const float* __restrict__ bases,
    const float* __restrict__ slopes)
{
    const float NORM_MAX = 1.0f - 1e-6f;
    size_t i4 = (size_t)blockIdx.x * blockDim.x + threadIdx.x;   // one float4
    float4 xv = reinterpret_cast<const float4*>(x)[i4];
    int d0 = (int)((i4 * 4) & (D_DIM - 1));
    float xs[4] = {xv.x, xv.y, xv.z, xv.w};
    union { __nv_bfloat16 h[4]; uint2 v; } hi, lo;
#pragma unroll
    for (int j = 0; j < 4; j++) {
        // bit-exact op order vs reference: (x+1)*0.5 (== /2), clip, *16 (exact), trunc
        float xn = (xs[j] + 1.0f) * 0.5f;
        xn = fminf(fmaxf(xn, 0.0f), NORM_MAX);
        float t = xn * 16.0f;
        int idx = (int)t;
        idx = idx < 0 ? 0 : (idx > GRID_G - 1 ? GRID_G - 1 : idx);
        float xl = t - (float)idx;
        int fi = (d0 + j) * GRID_G + idx;
        float s = __ldg(bases + fi) + __ldg(slopes + fi) * xl;
        __nv_bfloat16 h = __float2bfloat16(s);
        hi.h[j] = h;
        lo.h[j] = __float2bfloat16(s - __bfloat162float(h));
    }
    reinterpret_cast<uint2*>(g_A_hi)[i4] = hi.v;
    reinterpret_cast<uint2*>(g_A_lo)[i4] = lo.v;
}

// ---------------- kernel 2: mix hi/lo split --------------------
__global__ void __launch_bounds__(256) mix_split_kernel(const float* __restrict__ mix)
{
    size_t i4 = (size_t)blockIdx.x * blockDim.x + threadIdx.x;
    float4 mv = reinterpret_cast<const float4*>(mix)[i4];
    float ms[4] = {mv.x, mv.y, mv.z, mv.w};
    union { __nv_bfloat16 h[4]; uint2 v; } hi, lo;
#pragma unroll
    for (int j = 0; j < 4; j++) {
        __nv_bfloat16 h = __float2bfloat16(ms[j]);
        hi.h[j] = h;
        lo.h[j] = __float2bfloat16(ms[j] - __bfloat162float(h));
    }
    reinterpret_cast<uint2*>(g_M_hi)[i4] = hi.v;
    reinterpret_cast<uint2*>(g_M_lo)[i4] = lo.v;
}

// ---------------- GEMM: mma.sync bf16, split precision over virtual K=1536 -------
static constexpr int BM = 128;
static constexpr int BN = 128;
static constexpr int BK = 64;                      // bf16 per K-chunk
static constexpr int NSTAGE = 3;
static constexpr int K_VIRT = 3 * D_DIM;           // 1536
static constexpr int N_ITERS = K_VIRT / BK;        // 24
static constexpr int STAGE_BYTES = (BM + BN) * BK * 2;   // 32 KB
static constexpr int SMEM_BYTES = NSTAGE * STAGE_BYTES;  // 96 KB

__device__ __forceinline__ uint32_t smem_u32(const void* p) {
    uint32_t a;
    asm("{ .reg .u64 t; cvta.to.shared.u64 t, %1; cvt.u32.u64 %0, t; }" : "=r"(a) : "l"(p));
    return a;
}
__device__ __forceinline__ void cp_async16(uint32_t dst, const void* src) {
    asm volatile("cp.async.cg.shared.global [%0], [%1], 16;" :: "r"(dst), "l"(src));
}
#define CP_COMMIT() asm volatile("cp.async.commit_group;" ::: "memory")
template<int N>
__device__ __forceinline__ void cp_wait() {
    asm volatile("cp.async.wait_group %0;" :: "n"(N) : "memory");
}
__device__ __forceinline__ void ldsm_x4(uint32_t (&r)[4], uint32_t addr) {
    asm volatile("ldmatrix.sync.aligned.m8n8.x4.shared.b16 {%0,%1,%2,%3}, [%4];"
                 : "=r"(r[0]), "=r"(r[1]), "=r"(r[2]), "=r"(r[3]) : "r"(addr));
}
__device__ __forceinline__ void mma_16816(float (&c)[4], const uint32_t (&a)[4],
                                          uint32_t b0, uint32_t b1) {
    asm volatile(
        "mma.sync.aligned.m16n8k16.row.col.f32.bf16.bf16.f32 "
        "{%0,%1,%2,%3}, {%4,%5,%6,%7}, {%8,%9}, {%0,%1,%2,%3};"
        : "+f"(c[0]), "+f"(c[1]), "+f"(c[2]), "+f"(c[3])
        : "r"(a[0]), "r"(a[1]), "r"(a[2]), "r"(a[3]), "r"(b0), "r"(b1));
}

// smem tile layout: row-major [rows][BK] bf16, 128B rows, 16B chunks XOR-swizzled:
// chunk c of row r stored at chunk (c ^ (r & 7)).
__device__ __forceinline__ uint32_t tile_addr(uint32_t base, int row, int kchunk) {
    return base + row * 128 + (((uint32_t)kchunk ^ ((uint32_t)row & 7)) << 4);
}

__global__ void __launch_bounds__(256, 2) kan_gemm_kernel(
    const float* __restrict__ bias, float* __restrict__ out)
{
    extern __shared__ uint8_t smem[];
    const int tid  = threadIdx.x;
    const int wid  = tid >> 5;
    const int lane = tid & 31;
    const int m_base = blockIdx.y * BM;
    const int n_base = blockIdx.x * BN;
    const int wm = (wid & 1) * 64;         // warp row offset   (2 warps in M)
    const int wn = (wid >> 1) * 32;        // warp col offset   (4 warps in N)

    const uint32_t smem_base = smem_u32(smem);

    // per-stage bases
    uint32_t sA[NSTAGE], sB[NSTAGE];
#pragma unroll
    for (int s = 0; s < NSTAGE; s++) {
        sA[s] = smem_base + s * STAGE_BYTES;
        sB[s] = sA[s] + BM * BK * 2;
    }

    // ---- loader: 8 x 16B chunks per thread per stage (A:4, B:4) ----
    auto load_stage = [&](int stage, int it) {
        const int seg  = it >> 3;                 // 0:hi*hi 1:hi*lo 2:lo*hi
        const int koff = (it & 7) * BK;
        const __nv_bfloat16* Ap = (seg == 2) ? g_A_lo : g_A_hi;
        const __nv_bfloat16* Bp = (seg == 1) ? g_M_lo : g_M_hi;
#pragma unroll
        for (int j = 0; j < 4; j++) {
            int ch  = tid + j * 256;              // 0..1023
            int row = ch >> 3, c = ch & 7;
            cp_async16(tile_addr(sA[stage], row, c),
                       Ap + (size_t)(m_base + row) * D_DIM + koff + c * 8);
        }
#pragma unroll
        for (int j = 0; j < 4; j++) {
            int ch  = tid + j * 256;
            int row = ch >> 3, c = ch & 7;
            cp_async16(tile_addr(sB[stage], row, c),
                       Bp + (size_t)(n_base + row) * D_DIM + koff + c * 8);
        }
    };

    float acc[4][4][4];
#pragma unroll
    for (int i = 0; i < 4; i++)
#pragma unroll
        for (int j = 0; j < 4; j++)
#pragma unroll
            for (int k = 0; k < 4; k++) acc[i][j][k] = 0.0f;

    // prologue: fill 2 stages
    load_stage(0, 0); CP_COMMIT();
    load_stage(1, 1); CP_COMMIT();

    for (int it = 0; it < N_ITERS; it++) {
        cp_wait<1>();
        __syncthreads();

        const uint32_t a_base = sA[it % NSTAGE];
        const uint32_t b_base = sB[it % NSTAGE];

#pragma unroll
        for (int s = 0; s < BK / 16; s++) {       // 4 k16 steps
            // A fragments: 4 m-frags of m16k16
            uint32_t afr[4][4];
#pragma unroll
            for (int mf = 0; mf < 4; mf++) {
                int row = wm + mf * 16 + (lane & 15);
                int kc  = 2 * s + (lane >> 4);
                ldsm_x4(afr[mf], tile_addr(a_base, row, kc));
            }
            // B fragments: 2 x ldmatrix.x4, each covering 2 n-frags (n16 x k16)
            uint32_t bfr[4][2];
#pragma unroll
            for (int h = 0; h < 2; h++) {
                int row = wn + h * 16 + (lane & 7) + ((lane >> 4) << 3);
                int kc  = 2 * s + ((lane >> 3) & 1);
                uint32_t r[4];
                ldsm_x4(r, tile_addr(b_base, row, kc));
                bfr[h * 2 + 0][0] = r[0]; bfr[h * 2 + 0][1] = r[1];
                bfr[h * 2 + 1][0] = r[2]; bfr[h * 2 + 1][1] = r[3];
            }
#pragma unroll
            for (int mf = 0; mf < 4; mf++)
#pragma unroll
                for (int nf = 0; nf < 4; nf++)
                    mma_16816(acc[mf][nf], afr[mf], bfr[nf][0], bfr[nf][1]);
        }

        if (it + 2 < N_ITERS) load_stage((it + 2) % NSTAGE, it + 2);
        CP_COMMIT();
    }

    // ---- epilogue: add bias, store fp32 ----
    const int tg = lane & 3;        // thread-in-group
    const int gp = lane >> 2;       // group id (row within frag)
#pragma unroll
    for (int mf = 0; mf < 4; mf++) {
#pragma unroll
        for (int nf = 0; nf < 4; nf++) {
            int n = n_base + wn + nf * 8 + tg * 2;
            float b0 = __ldg(bias + n);
            float b1 = __ldg(bias + n + 1);
            int m0 = m_base + wm + mf * 16 + gp;
            float2 v0 = make_float2(acc[mf][nf][0] + b0, acc[mf][nf][1] + b1);
            float2 v1 = make_float2(acc[mf][nf][2] + b0, acc[mf][nf][3] + b1);
            *reinterpret_cast<float2*>(out + (size_t)m0 * O_DIM + n)       = v0;
            *reinterpret_cast<float2*>(out + (size_t)(m0 + 8) * O_DIM + n) = v1;
        }
    }
}

// ---------------- launch --------------------
extern "C" void kernel_launch(void* const* d_in, const int* in_sizes, int n_in,
                              void* d_out, int out_size) {
    const float* x      = (const float*)d_in[0];
    const float* bases  = (const float*)d_in[1];
    const float* slopes = (const float*)d_in[2];
    const float* mix    = (const float*)d_in[3];
    const float* bias   = (const float*)d_in[4];
    float* out = (float*)d_out;

    cudaFuncSetAttribute(kan_gemm_kernel,
                         cudaFuncAttributeMaxDynamicSharedMemorySize, SMEM_BYTES);

    spline_split_kernel<<<(B_ROWS * D_DIM / 4) / 256, 256>>>(x, bases, slopes);
    mix_split_kernel<<<(O_DIM * D_DIM / 4) / 256, 256>>>(mix);

    dim3 grid(O_DIM / BN, B_ROWS / BM);   // n-tiles fastest for L2 reuse of A
    kan_gemm_kernel<<<grid, 256, SMEM_BYTES>>>(bias, out);
}

// round 3
// speedup vs baseline: 2.0884x; 2.0884x over previous
#include <cuda_runtime.h>
#include <cuda_fp16.h>
#include <cstdint>

// ---------------- problem constants ----------------
static constexpr int B_ROWS = 65536;
static constexpr int D_DIM  = 512;   // K
static constexpr int O_DIM  = 512;   // N
static constexpr int GRID_G = 16;

// ---------------- scratch (no allocs allowed) ----------------
__device__ __half g_A_h[(size_t)B_ROWS * D_DIM];
__device__ __half g_M_h[(size_t)O_DIM * D_DIM];
__device__ float2 g_tab[D_DIM * GRID_G];     // (base, slope) packed

// ---------------- kernel 0: pack (base,slope) table --------------------
__global__ void __launch_bounds__(256) pack_table_kernel(
    const float* __restrict__ bases, const float* __restrict__ slopes)
{
    int i = blockIdx.x * blockDim.x + threadIdx.x;   // 0..8191
    g_tab[i] = make_float2(bases[i], slopes[i]);
}

// ---------------- kernel 1: spline -> fp16 --------------------
__global__ void __launch_bounds__(256) spline_kernel(const float* __restrict__ x)
{
    const float NORM_MAX = 1.0f - 1e-6f;
    size_t i4 = (size_t)blockIdx.x * blockDim.x + threadIdx.x;   // one float4
    float4 xv = reinterpret_cast<const float4*>(x)[i4];
    int d0 = (int)((i4 * 4) & (D_DIM - 1));
    float xs[4] = {xv.x, xv.y, xv.z, xv.w};
    union { __half h[4]; uint2 v; } o;
#pragma unroll
    for (int j = 0; j < 4; j++) {
        // bit-exact op order vs reference: (x+1)*0.5 (== /2), clip, *16 (exact), trunc
        float xn = (xs[j] + 1.0f) * 0.5f;
        xn = fminf(fmaxf(xn, 0.0f), NORM_MAX);
        float t = xn * 16.0f;
        int idx = (int)t;
        idx = idx < 0 ? 0 : (idx > GRID_G - 1 ? GRID_G - 1 : idx);
        float xl = t - (float)idx;
        float2 bs = __ldg(&g_tab[(d0 + j) * GRID_G + idx]);
        o.h[j] = __float2half_rn(bs.x + bs.y * xl);
    }
    reinterpret_cast<uint2*>(g_A_h)[i4] = o.v;
}

// ---------------- kernel 2: mix -> fp16 --------------------
__global__ void __launch_bounds__(256) mix_half_kernel(const float* __restrict__ mix)
{
    size_t i4 = (size_t)blockIdx.x * blockDim.x + threadIdx.x;
    float4 mv = reinterpret_cast<const float4*>(mix)[i4];
    union { __half h[4]; uint2 v; } o;
    o.h[0] = __float2half_rn(mv.x);
    o.h[1] = __float2half_rn(mv.y);
    o.h[2] = __float2half_rn(mv.z);
    o.h[3] = __float2half_rn(mv.w);
    reinterpret_cast<uint2*>(g_M_h)[i4] = o.v;
}

// ---------------- GEMM: mma.sync fp16, fp32 accumulate, K=512 -------
static constexpr int BM = 128;
static constexpr int BN = 128;
static constexpr int BK = 64;                      // fp16 per K-chunk
static constexpr int NSTAGE = 3;
static constexpr int N_ITERS = D_DIM / BK;         // 8
static constexpr int STAGE_BYTES = (BM + BN) * BK * 2;   // 32 KB
static constexpr int SMEM_BYTES = NSTAGE * STAGE_BYTES;  // 96 KB

__device__ __forceinline__ uint32_t smem_u32(const void* p) {
    uint32_t a;
    asm("{ .reg .u64 t; cvta.to.shared.u64 t, %1; cvt.u32.u64 %0, t; }" : "=r"(a) : "l"(p));
    return a;
}
__device__ __forceinline__ void cp_async16(uint32_t dst, const void* src) {
    asm volatile("cp.async.cg.shared.global [%0], [%1], 16;" :: "r"(dst), "l"(src));
}
#define CP_COMMIT() asm volatile("cp.async.commit_group;" ::: "memory")
template<int N>
__device__ __forceinline__ void cp_wait() {
    asm volatile("cp.async.wait_group %0;" :: "n"(N) : "memory");
}
__device__ __forceinline__ void ldsm_x4(uint32_t (&r)[4], uint32_t addr) {
    asm volatile("ldmatrix.sync.aligned.m8n8.x4.shared.b16 {%0,%1,%2,%3}, [%4];"
                 : "=r"(r[0]), "=r"(r[1]), "=r"(r[2]), "=r"(r[3]) : "r"(addr));
}
__device__ __forceinline__ void mma_16816(float (&c)[4], const uint32_t (&a)[4],
                                          uint32_t b0, uint32_t b1) {
    asm volatile(
        "mma.sync.aligned.m16n8k16.row.col.f32.f16.f16.f32 "
        "{%0,%1,%2,%3}, {%4,%5,%6,%7}, {%8,%9}, {%0,%1,%2,%3};"
        : "+f"(c[0]), "+f"(c[1]), "+f"(c[2]), "+f"(c[3])
        : "r"(a[0]), "r"(a[1]), "r"(a[2]), "r"(a[3]), "r"(b0), "r"(b1));
}

// smem tile layout: row-major [rows][BK] fp16, 128B rows, 16B chunks XOR-swizzled.
__device__ __forceinline__ uint32_t tile_addr(uint32_t base, int row, int kchunk) {
    return base + row * 128 + (((uint32_t)kchunk ^ ((uint32_t)row & 7)) << 4);
}

__global__ void __launch_bounds__(256, 2) kan_gemm_kernel(
    const float* __restrict__ bias, float* __restrict__ out)
{
    extern __shared__ uint8_t smem[];
    const int tid  = threadIdx.x;
    const int wid  = tid >> 5;
    const int lane = tid & 31;
    const int m_base = blockIdx.y * BM;
    const int n_base = blockIdx.x * BN;
    const int wm = (wid & 1) * 64;         // 2 warps in M
    const int wn = (wid >> 1) * 32;        // 4 warps in N

    const uint32_t smem_base = smem_u32(smem);
    uint32_t sA[NSTAGE], sB[NSTAGE];
#pragma unroll
    for (int s = 0; s < NSTAGE; s++) {
        sA[s] = smem_base + s * STAGE_BYTES;
        sB[s] = sA[s] + BM * BK * 2;
    }

    auto load_stage = [&](int stage, int it) {
        const int koff = it * BK;
#pragma unroll
        for (int j = 0; j < 4; j++) {
            int ch  = tid + j * 256;              // 0..1023
            int row = ch >> 3, c = ch & 7;
            cp_async16(tile_addr(sA[stage], row, c),
                       g_A_h + (size_t)(m_base + row) * D_DIM + koff + c * 8);
        }
#pragma unroll
        for (int j = 0; j < 4; j++) {
            int ch  = tid + j * 256;
            int row = ch >> 3, c = ch & 7;
            cp_async16(tile_addr(sB[stage], row, c),
                       g_M_h + (size_t)(n_base + row) * D_DIM + koff + c * 8);
        }
    };

    float acc[4][4][4];
#pragma unroll
    for (int i = 0; i < 4; i++)
#pragma unroll
        for (int j = 0; j < 4; j++)
#pragma unroll
            for (int k = 0; k < 4; k++) acc[i][j][k] = 0.0f;

    load_stage(0, 0); CP_COMMIT();
    load_stage(1, 1); CP_COMMIT();

    for (int it = 0; it < N_ITERS; it++) {
        cp_wait<1>();
        __syncthreads();

        const uint32_t a_base = sA[it % NSTAGE];
        const uint32_t b_base = sB[it % NSTAGE];

#pragma unroll
        for (int s = 0; s < BK / 16; s++) {       // 4 k16 steps
            uint32_t afr[4][4];
#pragma unroll
            for (int mf = 0; mf < 4; mf++) {
                int row = wm + mf * 16 + (lane & 15);
                int kc  = 2 * s + (lane >> 4);
                ldsm_x4(afr[mf], tile_addr(a_base, row, kc));
            }
            uint32_t bfr[4][2];
#pragma unroll
            for (int h = 0; h < 2; h++) {
                int row = wn + h * 16 + (lane & 7) + ((lane >> 4) << 3);
                int kc  = 2 * s + ((lane >> 3) & 1);
                uint32_t r[4];
                ldsm_x4(r, tile_addr(b_base, row, kc));
                bfr[h * 2 + 0][0] = r[0]; bfr[h * 2 + 0][1] = r[1];
                bfr[h * 2 + 1][0] = r[2]; bfr[h * 2 + 1][1] = r[3];
            }
#pragma unroll
            for (int mf = 0; mf < 4; mf++)
#pragma unroll
                for (int nf = 0; nf < 4; nf++)
                    mma_16816(acc[mf][nf], afr[mf], bfr[nf][0], bfr[nf][1]);
        }

        if (it + 2 < N_ITERS) load_stage((it + 2) % NSTAGE, it + 2);
        CP_COMMIT();
    }

    // ---- epilogue: add bias, store fp32 ----
    const int tg = lane & 3;
    const int gp = lane >> 2;
#pragma unroll
    for (int mf = 0; mf < 4; mf++) {
#pragma unroll
        for (int nf = 0; nf < 4; nf++) {
            int n = n_base + wn + nf * 8 + tg * 2;
            float b0 = __ldg(bias + n);
            float b1 = __ldg(bias + n + 1);
            int m0 = m_base + wm + mf * 16 + gp;
            float2 v0 = make_float2(acc[mf][nf][0] + b0, acc[mf][nf][1] + b1);
            float2 v1 = make_float2(acc[mf][nf][2] + b0, acc[mf][nf][3] + b1);
            *reinterpret_cast<float2*>(out + (size_t)m0 * O_DIM + n)       = v0;
            *reinterpret_cast<float2*>(out + (size_t)(m0 + 8) * O_DIM + n) = v1;
        }
    }
}

// ---------------- launch --------------------
extern "C" void kernel_launch(void* const* d_in, const int* in_sizes, int n_in,
                              void* d_out, int out_size) {
    const float* x      = (const float*)d_in[0];
    const float* bases  = (const float*)d_in[1];
    const float* slopes = (const float*)d_in[2];
    const float* mix    = (const float*)d_in[3];
    const float* bias   = (const float*)d_in[4];
    float* out = (float*)d_out;

    cudaFuncSetAttribute(kan_gemm_kernel,
                         cudaFuncAttributeMaxDynamicSharedMemorySize, SMEM_BYTES);

    pack_table_kernel<<<(D_DIM * GRID_G) / 256, 256>>>(bases, slopes);
    spline_kernel<<<(B_ROWS * D_DIM / 4) / 256, 256>>>(x);
    mix_half_kernel<<<(O_DIM * D_DIM / 4) / 256, 256>>>(mix);

    dim3 grid(O_DIM / BN, B_ROWS / BM);   // n-tiles fastest for L2 reuse of A
    kan_gemm_kernel<<<grid, 256, SMEM_BYTES>>>(bias, out);
}